// round 11
// baseline (speedup 1.0000x reference)
#include <cuda_runtime.h>
#include <cstdint>

#define BB 128
#define NN 16384
#define KK 32
#define CAP 2048                       // per-row candidate cap (bench needs ~100)
#define THR 2.5f                       // fast-path threshold
#define NBINS 4096                     // fallback histogram
#define TPB 256
#define BPT (NBINS / TPB)              // 16 bins per thread (fallback scan)

#define ZSEG 512                       // n-positions per CTA
#define SEGS (NN / ZSEG)               // 32 CTAs per row
#define ZGRID (BB * SEGS)              // 4096
#define ZF4_PER_T (ZSEG * KK / 4 / TPB)  // 16 float4 stores per thread

// eps = FLT_EPSILON = 2^-23 ; eps^2 = 2^-46 ; 1/eps^2 = 2^46 (exact powers of 2)
#define EPSf    1.1920929e-07f
#define E2f     1.4210854715202004e-14f
#define INV_E2f 7.0368744177664e13f

// Device scratch (allocation-free rule: __device__ globals; zero-initialized;
// g_cnt/g_done are reset by the last CTA each launch for graph replays).
__device__ float    g_cand[BB * CAP];
__device__ unsigned g_cidx[BB * CAP];
__device__ unsigned g_cnt[BB];
__device__ unsigned g_done[BB];

__device__ __forceinline__ unsigned key_of(float f) {
    unsigned u = __float_as_uint(f);
    return (u & 0x80000000u) ? ~u : (u | 0x80000000u);
}
__device__ __forceinline__ float key_to_float(unsigned k) {
    unsigned u = (k & 0x80000000u) ? (k & 0x7FFFFFFFu) : ~k;
    return __uint_as_float(u);
}

// ---------------------------------------------------------------------------
// Single fused kernel:
//   phase 1 (all 4096 CTAs): streaming zero-fill of this CTA's 64 KB output
//     slab (exact for non-candidates: s_j >= 1 -> relu(1-s_j) == 0), fused
//     with threshold-collect of the matching 512 x's (x >= THR is a provable
//     superset of the exact top-32 and of every eps-window contributor, since
//     ulp(THR) > eps).
//   phase 2 (last CTA per row only, via threadfence+atomic ticket): exact
//     rank-select of the top-32, c_j = 1 - x_m_sum_j (terms exactly 0/1 ->
//     order-invariant), scatter of candidate segments; overlaps the store
//     stream of the remaining CTAs. Exact histogram fallback for non-bench
//     inputs lives here too.
// ---------------------------------------------------------------------------
__global__ void __launch_bounds__(TPB) fused_kernel(const float* __restrict__ x,
                                                    float* __restrict__ out) {
    extern __shared__ unsigned char sraw[];
    float*    cand = (float*)sraw;                   // 8 KB
    unsigned* cidx = (unsigned*)(sraw + CAP * 4);    // 8 KB
    unsigned* hist = (unsigned*)(sraw + CAP * 8);    // 16 KB (fallback only)
    __shared__ unsigned csum[TPB];
    __shared__ float st[KK], sc[KK];
    __shared__ float partial[8 * KK];
    __shared__ unsigned s_m;
    __shared__ int s_bin, s_last;

    const int cid  = blockIdx.x;          // b*32 + seg
    const int b    = cid >> 5;
    const int n0   = (cid & 31) * ZSEG;
    const int tid  = threadIdx.x;
    const int lane = tid & 31;

    // Kick off the x loads (2 floats/thread, coalesced); hidden under stores.
    const float2 xv = ((const float2*)(x + (size_t)b * NN + n0))[tid];

    // ---- Zero this CTA's 64 KB output slab (streaming stores) ----
    const float4 z = make_float4(0.f, 0.f, 0.f, 0.f);
    float4* basep = (float4*)out + ((size_t)b * NN + n0) * (KK / 4) + tid;
    #pragma unroll
    for (int k = 0; k < ZF4_PER_T; k++)
        __stcs(basep + k * TPB, z);

    // ---- Threshold collect: ballot-aggregated global append ----
    float vals[2] = {xv.x, xv.y};
    #pragma unroll
    for (int c = 0; c < 2; c++) {
        const bool pred = vals[c] >= THR;
        const unsigned bm = __ballot_sync(0xFFFFFFFFu, pred);
        if (bm) {
            const int leader = __ffs(bm) - 1;
            unsigned basec = 0;
            if (lane == leader) basec = atomicAdd(&g_cnt[b], (unsigned)__popc(bm));
            basec = __shfl_sync(0xFFFFFFFFu, basec, leader);
            if (pred) {
                const unsigned p = basec + (unsigned)__popc(bm & ((1u << lane) - 1u));
                if (p < CAP) {
                    g_cand[b * CAP + p] = vals[c];
                    g_cidx[b * CAP + p] = (unsigned)(n0 + 2 * tid + c);
                }
            }
        }
    }

    // ---- Ticket: release all prior stores, last CTA of the row finalizes ----
    __threadfence();
    __syncthreads();
    if (tid == 0) {
        unsigned old = atomicAdd(&g_done[b], 1u);
        s_last = (old == SEGS - 1);
    }
    __syncthreads();
    if (!s_last) return;
    __threadfence();                      // acquire side

    if (tid == 0) {
        s_m = g_cnt[b];
        g_cnt[b]  = 0;                    // reset for next graph replay
        g_done[b] = 0;
    }
    __syncthreads();
    unsigned cnt = s_m;

    if (cnt >= KK && cnt <= CAP) {
        // Fast path: candidates are L2-hot (just written by this row's CTAs).
        for (unsigned i = tid; i < cnt; i += TPB) {
            cand[i] = g_cand[b * CAP + i];
            cidx[i] = g_cidx[b * CAP + i];
        }
        __syncthreads();
    } else {
        // ---- Exact fallback: 12-bit histogram select over the full row ----
        const float* xrow = x + (size_t)b * NN;
        for (int i = tid; i < NBINS; i += TPB) hist[i] = 0;
        if (tid == 0) s_m = 0;
        __syncthreads();
        for (int i = tid; i < NN; i += TPB) {
            unsigned dg = key_of(xrow[i]) >> 20;
            unsigned peers = __match_any_sync(0xFFFFFFFFu, dg);
            if ((tid & 31) == __ffs(peers) - 1)
                atomicAdd(&hist[dg], (unsigned)__popc(peers));
        }
        __syncthreads();
        {
            unsigned s = 0;
            #pragma unroll
            for (int j = 0; j < BPT; j++) s += hist[tid * BPT + j];
            csum[tid] = s;
            __syncthreads();
            #pragma unroll
            for (int off = 1; off < TPB; off <<= 1) {
                unsigned t = (tid + off < TPB) ? csum[tid + off] : 0u;
                __syncthreads();
                csum[tid] += t;
                __syncthreads();
            }
        }
        {
            unsigned incl = csum[tid];
            unsigned excl = (tid < TPB - 1) ? csum[tid + 1] : 0u;
            if (incl >= KK && excl < KK) {
                unsigned cum = excl;
                #pragma unroll
                for (int j = BPT - 1; j >= 0; j--) {
                    cum += hist[tid * BPT + j];
                    if (cum >= KK) { s_bin = tid * BPT + j; break; }
                }
            }
        }
        __syncthreads();
        const float binlo   = key_to_float((unsigned)s_bin << 20);
        const unsigned thrk = key_of(binlo - 2.0f * EPSf);
        for (int i = tid; i < NN; i += TPB) {
            float v = xrow[i];
            if (key_of(v) >= thrk) {
                unsigned p = atomicAdd(&s_m, 1u);
                if (p < CAP) { cand[p] = v; cidx[p] = (unsigned)i; }
            }
        }
        __syncthreads();
        cnt = min(s_m, (unsigned)CAP);
    }
    const int m = (int)cnt;

    // ---- Rank-select top-32 (descending) among m candidates ----
    for (int i0 = tid; i0 < m; i0 += TPB) {
        unsigned kv = key_of(cand[i0]);
        int rank = 0;
        for (int i = 0; i < m; i++) {
            unsigned kw = key_of(cand[i]);
            rank += (kw > kv) || (kw == kv && i < i0);
        }
        if (rank < KK) st[rank] = cand[i0];
    }
    __syncthreads();

    // ---- c_j = 1 - x_m_sum_j, parallel: thread t = (chunk t>>5, j = t&31) ----
    {
        const int j = tid & 31, ck = tid >> 5;
        const float tj = st[j];
        float acc = 0.f;
        for (int i = ck; i < m; i += 8) {
            float d = cand[i] - tj;
            acc += fmaxf(__fmaf_rn(-d, d, E2f), 0.f) * INV_E2f;
        }
        partial[tid] = acc;               // [ck][j] at ck*32 + j == tid
    }
    __syncthreads();
    if (tid < KK) {
        float acc = 0.f;
        #pragma unroll
        for (int ck = 0; ck < 8; ck++) acc += partial[ck * KK + tid];
        sc[tid] = 1.0f - acc;             // exact: terms are exactly 0 or 1
    }
    __syncthreads();

    // ---- Scatter: rewrite the 32-wide segment of each candidate position ----
    for (int w = tid; w < m * 8; w += TPB) {
        const int p = w >> 3, q = w & 7, j0 = q * 4;
        const float xvv    = cand[p];
        const unsigned idx = cidx[p];
        float d;
        float4 r;
        d = xvv - st[j0 + 0]; r.x = fmaxf(__fmaf_rn(fmaxf(__fmaf_rn(-d, d, E2f), 0.f), INV_E2f, sc[j0 + 0]), 0.f);
        d = xvv - st[j0 + 1]; r.y = fmaxf(__fmaf_rn(fmaxf(__fmaf_rn(-d, d, E2f), 0.f), INV_E2f, sc[j0 + 1]), 0.f);
        d = xvv - st[j0 + 2]; r.z = fmaxf(__fmaf_rn(fmaxf(__fmaf_rn(-d, d, E2f), 0.f), INV_E2f, sc[j0 + 2]), 0.f);
        d = xvv - st[j0 + 3]; r.w = fmaxf(__fmaf_rn(fmaxf(__fmaf_rn(-d, d, E2f), 0.f), INV_E2f, sc[j0 + 3]), 0.f);
        float4* dst = (float4*)(out + ((size_t)b * NN + idx) * KK);
        dst[q] = r;
    }
}

// ---------------------------------------------------------------------------
extern "C" void kernel_launch(void* const* d_in, const int* in_sizes, int n_in,
                              void* d_out, int out_size) {
    const float* x = (const float*)d_in[0];
    float* out = (float*)d_out;
    (void)in_sizes; (void)n_in; (void)out_size;   // shapes fixed: (128,16384), k=32

    const int smem = CAP * 8 + NBINS * 4;         // 32 KB (cand | cidx | hist)
    cudaFuncSetAttribute(fused_kernel,
                         cudaFuncAttributeMaxDynamicSharedMemorySize, smem);

    fused_kernel<<<ZGRID, TPB, smem>>>(x, out);
}